// round 2
// baseline (speedup 1.0000x reference)
#include <cuda_runtime.h>
#include <cuda_bf16.h>
#include <cstdint>

// Problem constants
#define Bsz 8
#define Tn  2048
#define BT  (Bsz*Tn)      // 16384 tokens
#define Gg  8
#define Dd  64
#define Vv  1024
#define GD  512           // G*D

// Tiling
#define TM 64             // tokens per block
#define TN 128            // codewords per smem chunk
#define PADM 68           // padded token stride for xs (68%4==0 keeps float4 alignment)
#define NCHUNK (Vv/TN)    // 8

// Output layout: concat(ids[BT*G], quantized_st[BT*GD], kmeans, commitment, total) as f32
#define N_IDS   (BT*Gg)            // 131072
#define OUT_Q   N_IDS
#define N_Q     (BT*GD)            // 8388608
#define OUT_LOSS (N_IDS + N_Q)     // 8519680

__device__ float g_csq[Gg*Vv];       // c_sq, laid out [g][v]
__device__ float g_partials[2048];   // per-block loss partials (8 groups * 256 tiles)

// ---------------------------------------------------------------------------
// Kernel 0: c_sq[v,g] = sum_d codebook[v,g,d]^2, stored [g][v]
// ---------------------------------------------------------------------------
__global__ void csq_kernel(const float* __restrict__ cb) {
    int idx = blockIdx.x * blockDim.x + threadIdx.x;   // 0..8191
    if (idx >= Vv * Gg) return;
    int v = idx >> 3;
    int g = idx & 7;
    const float4* p = (const float4*)(cb + (size_t)v * GD + g * Dd);
    float s = 0.f;
#pragma unroll
    for (int i = 0; i < 16; i++) {
        float4 c = p[i];
        s = fmaf(c.x, c.x, s);
        s = fmaf(c.y, c.y, s);
        s = fmaf(c.z, c.z, s);
        s = fmaf(c.w, c.w, s);
    }
    g_csq[g * Vv + v] = s;
}

// ---------------------------------------------------------------------------
// Kernel 1: fused GEMM + argmin + quantized write + loss partial
// Grid: (BT/TM = 256, G = 8), 256 threads.
// Thread grid: tm = tid>>5 (8 token-rows of 8), tn = tid&31 (32 cword-cols of 4)
// Each thread: 8 tokens x 4 codewords register tile per chunk.
// ---------------------------------------------------------------------------
__global__ __launch_bounds__(256)
void vq_kernel(const float* __restrict__ x, const int* __restrict__ pad,
               const float* __restrict__ cb, float* __restrict__ out)
{
    extern __shared__ float sm[];
    float* xs    = sm;                         // [Dd][PADM]   transposed x tile
    float* cs    = xs + Dd * PADM;             // [Dd][TN]     transposed codebook chunk
    float* csq   = cs + Dd * TN;               // [Vv]
    int*   ids_s = (int*)(csq + Vv);           // [TM]
    float* msk_s = (float*)(ids_s + TM);       // [TM]
    float* red   = msk_s + TM;                 // [8]

    const int tid = threadIdx.x;
    const int tm  = tid >> 5;
    const int tn  = tid & 31;
    const int g   = blockIdx.y;
    const int bt0 = blockIdx.x * TM;

    // ---- load x tile (64 tokens x 64 d), transposed into xs[d][m] ----
    {
        const float* xg = x + (size_t)bt0 * GD + g * Dd;
#pragma unroll
        for (int it = 0; it < 4; it++) {
            int i  = it * 256 + tid;        // 0..1023
            int m  = i >> 4;                // token 0..63
            int d4 = i & 15;                // float4 index 0..15
            float4 v4 = *(const float4*)(xg + (size_t)m * GD + d4 * 4);
            xs[(d4 * 4 + 0) * PADM + m] = v4.x;
            xs[(d4 * 4 + 1) * PADM + m] = v4.y;
            xs[(d4 * 4 + 2) * PADM + m] = v4.z;
            xs[(d4 * 4 + 3) * PADM + m] = v4.w;
        }
        for (int i = tid; i < Vv; i += 256) csq[i] = g_csq[g * Vv + i];
    }

    float mind[8];
    int   minv[8];
#pragma unroll
    for (int i = 0; i < 8; i++) { mind[i] = 3.4e38f; minv[i] = 0; }

    const float* cbg = cb + g * Dd;

    for (int ch = 0; ch < NCHUNK; ch++) {
        __syncthreads();   // prior chunk's reads done before overwriting cs
        // ---- load codebook chunk [TN cwords x 64 d], transposed into cs[d][v] ----
        {
            const int vbase = ch * TN;
#pragma unroll
            for (int it = 0; it < 8; it++) {
                int i  = it * 256 + tid;    // 0..2047
                int vl = i & 127;           // lane-major v -> conflict-free STS
                int d4 = i >> 7;            // 0..15
                float4 c4 = *(const float4*)(cbg + (size_t)(vbase + vl) * GD + d4 * 4);
                cs[(d4 * 4 + 0) * TN + vl] = c4.x;
                cs[(d4 * 4 + 1) * TN + vl] = c4.y;
                cs[(d4 * 4 + 2) * TN + vl] = c4.z;
                cs[(d4 * 4 + 3) * TN + vl] = c4.w;
            }
        }
        __syncthreads();

        float acc[8][4];
#pragma unroll
        for (int i = 0; i < 8; i++)
#pragma unroll
            for (int j = 0; j < 4; j++) acc[i][j] = 0.f;

        const float* asrc = xs + tm * 8;   // broadcast reads (all lanes same addr)
        const float* bsrc = cs + tn * 4;   // lanes stride 16B -> conflict-free
#pragma unroll 16
        for (int k = 0; k < Dd; k++) {
            float4 a0 = *(const float4*)(asrc + k * PADM);
            float4 a1 = *(const float4*)(asrc + k * PADM + 4);
            float4 b  = *(const float4*)(bsrc + k * TN);
            float av[8] = {a0.x, a0.y, a0.z, a0.w, a1.x, a1.y, a1.z, a1.w};
            float bv[4] = {b.x, b.y, b.z, b.w};
#pragma unroll
            for (int i = 0; i < 8; i++)
#pragma unroll
                for (int j = 0; j < 4; j++)
                    acc[i][j] = fmaf(av[i], bv[j], acc[i][j]);
        }

        // dist = c_sq - 2*dot; running argmin (ascending v within thread)
        const int vb = ch * TN + tn * 4;
#pragma unroll
        for (int j = 0; j < 4; j++) {
            float cq = csq[vb + j];
#pragma unroll
            for (int i = 0; i < 8; i++) {
                float d = fmaf(-2.f, acc[i][j], cq);
                if (d < mind[i]) { mind[i] = d; minv[i] = vb + j; }
            }
        }
    }

    // ---- warp argmin across 32 lanes (each warp = one tm row of 8 tokens) ----
#pragma unroll
    for (int i = 0; i < 8; i++) {
        float d = mind[i];
        int   v = minv[i];
        for (int off = 16; off; off >>= 1) {
            float d2 = __shfl_down_sync(0xffffffffu, d, off);
            int   v2 = __shfl_down_sync(0xffffffffu, v, off);
            if (d2 < d || (d2 == d && v2 < v)) { d = d2; v = v2; }
        }
        if (tn == 0) ids_s[tm * 8 + i] = v;
    }
    __syncthreads();

    // ---- ids output + mask ----
    if (tid < TM) {
        int bt = bt0 + tid;
        int p  = pad[bt];
        msk_s[tid] = p ? 0.f : 1.f;
        out[(size_t)bt * Gg + g] = p ? -1.0f : (float)ids_s[tid];
    }
    __syncthreads();

    // ---- quantized_st = q*mask, and masked ||q - x||^2 partial ----
    float ss = 0.f;
    {
        int tk   = tid >> 2;    // token 0..63 (4 threads per token)
        int part = tid & 3;
        int d0   = part * 16;
        int id   = ids_s[tk];
        float m  = msk_s[tk];
        int bt   = bt0 + tk;
        float*       qo = out + OUT_Q + ((size_t)bt * Gg + g) * Dd + d0;
        const float* qc = cb + (size_t)id * GD + g * Dd + d0;
#pragma unroll
        for (int q4 = 0; q4 < 4; q4++) {
            float4 qv = *(const float4*)(qc + q4 * 4);
            float xv0 = xs[(d0 + q4 * 4 + 0) * PADM + tk];
            float xv1 = xs[(d0 + q4 * 4 + 1) * PADM + tk];
            float xv2 = xs[(d0 + q4 * 4 + 2) * PADM + tk];
            float xv3 = xs[(d0 + q4 * 4 + 3) * PADM + tk];
            float e0 = qv.x - xv0, e1 = qv.y - xv1, e2 = qv.z - xv2, e3 = qv.w - xv3;
            ss += e0 * e0 + e1 * e1 + e2 * e2 + e3 * e3;
            float4 o;
            o.x = qv.x * m; o.y = qv.y * m; o.z = qv.z * m; o.w = qv.w * m;
            *(float4*)(qo + q4 * 4) = o;
        }
        ss *= m;
    }
    for (int off = 16; off; off >>= 1) ss += __shfl_down_sync(0xffffffffu, ss, off);
    if (tn == 0) red[tm] = ss;
    __syncthreads();
    if (tid == 0) {
        float s = 0.f;
#pragma unroll
        for (int i = 0; i < 8; i++) s += red[i];
        g_partials[blockIdx.y * gridDim.x + blockIdx.x] = s;
    }
}

// ---------------------------------------------------------------------------
// Kernel 2: final reduction -> 3 scalar losses
// ---------------------------------------------------------------------------
__global__ void final_kernel(const int* __restrict__ pad, float* __restrict__ out) {
    __shared__ float rs[256];
    __shared__ int   rc[256];
    int tid = threadIdx.x;
    float s = 0.f;
    for (int i = tid; i < 2048; i += 256) s += g_partials[i];
    int c = 0;
    for (int i = tid; i < BT; i += 256) c += (pad[i] == 0);
    rs[tid] = s; rc[tid] = c;
    __syncthreads();
    for (int off = 128; off; off >>= 1) {
        if (tid < off) { rs[tid] += rs[tid + off]; rc[tid] += rc[tid + off]; }
        __syncthreads();
    }
    if (tid == 0) {
        float denom = (float)rc[0];
        float k = rs[0] / denom;
        out[OUT_LOSS + 0] = k;        // kmeans_loss
        out[OUT_LOSS + 1] = k;        // commitment_loss (numerically identical)
        out[OUT_LOSS + 2] = k + k;    // total (BETA = 1)
    }
}

// ---------------------------------------------------------------------------
extern "C" void kernel_launch(void* const* d_in, const int* in_sizes, int n_in,
                              void* d_out, int out_size)
{
    const float* x   = (const float*)d_in[0];
    const int*   pad = (const int*)  d_in[1];
    const float* cb  = (const float*)d_in[2];
    float*       out = (float*)d_out;

    const int smem = (Dd * PADM + Dd * TN + Vv) * 4 + TM * 4 + TM * 4 + 8 * 4;
    cudaFuncSetAttribute(vq_kernel, cudaFuncAttributeMaxDynamicSharedMemorySize, smem);

    csq_kernel<<<32, 256>>>(cb);
    dim3 grid(BT / TM, Gg);
    vq_kernel<<<grid, 256, smem>>>(x, pad, cb, out);
    final_kernel<<<1, 256>>>(pad, out);
}

// round 3
// speedup vs baseline: 1.0248x; 1.0248x over previous
#include <cuda_runtime.h>
#include <cuda_bf16.h>
#include <cstdint>

// Problem constants
#define Bsz 8
#define Tn  2048
#define BT  (Bsz*Tn)      // 16384 tokens
#define Gg  8
#define Dd  64
#define Vv  1024
#define GD  512           // G*D

// Tiling
#define TM 64             // tokens per block
#define TN 128            // codewords per smem chunk
#define PADM 68           // padded token stride for xs (68%4==0 keeps float4 alignment)
#define NCHUNK (Vv/TN)    // 8

// Output layout: concat(ids[BT*G], quantized_st[BT*GD], kmeans, commitment, total) as f32
#define N_IDS   (BT*Gg)            // 131072
#define OUT_Q   N_IDS
#define N_Q     (BT*GD)            // 8388608
#define OUT_LOSS (N_IDS + N_Q)     // 8519680

// Packed fp32x2 FMA (FFMA2) — two exact fp32 FMAs per instruction (sm_100+).
#define FFMA2(d, a, b, c) \
    asm("fma.rn.f32x2 %0, %1, %2, %3;" : "=l"(d) : "l"(a), "l"(b), "l"(c))
#define PACK2DUP(d, x) \
    asm("mov.b64 %0, {%1, %1};" : "=l"(d) : "r"(__float_as_uint(x)))

__device__ float g_csq[Gg*Vv];       // c_sq, laid out [g][v]
__device__ float g_partials[2048];   // per-block loss partials (8 groups * 256 tiles)

// ---------------------------------------------------------------------------
// Kernel 0: c_sq[v,g] = sum_d codebook[v,g,d]^2, stored [g][v]
// ---------------------------------------------------------------------------
__global__ void csq_kernel(const float* __restrict__ cb) {
    int idx = blockIdx.x * blockDim.x + threadIdx.x;   // 0..8191
    if (idx >= Vv * Gg) return;
    int v = idx >> 3;
    int g = idx & 7;
    const float4* p = (const float4*)(cb + (size_t)v * GD + g * Dd);
    float s = 0.f;
#pragma unroll
    for (int i = 0; i < 16; i++) {
        float4 c = p[i];
        s = fmaf(c.x, c.x, s);
        s = fmaf(c.y, c.y, s);
        s = fmaf(c.z, c.z, s);
        s = fmaf(c.w, c.w, s);
    }
    g_csq[g * Vv + v] = s;
}

// ---------------------------------------------------------------------------
// Kernel 1: fused GEMM + argmin + quantized write + loss partial
// Grid: (BT/TM = 256, G = 8), 256 threads.
// Thread grid: tm = tid>>5 (8 token-rows of 8), tn = tid&31 (32 cword-cols of 4)
// Each thread: 8 tokens x 4 codewords register tile per chunk, computed as
// 4 token-PAIRS x 4 codewords with packed fp32x2 FMAs.
// ---------------------------------------------------------------------------
__global__ __launch_bounds__(256)
void vq_kernel(const float* __restrict__ x, const int* __restrict__ pad,
               const float* __restrict__ cb, float* __restrict__ out)
{
    extern __shared__ float sm[];
    float* xs    = sm;                         // [Dd][PADM]   transposed x tile
    float* cs    = xs + Dd * PADM;             // [Dd][TN]     transposed codebook chunk
    float* csq   = cs + Dd * TN;               // [Vv]
    int*   ids_s = (int*)(csq + Vv);           // [TM]
    float* msk_s = (float*)(ids_s + TM);       // [TM]
    float* red   = msk_s + TM;                 // [8]

    const int tid = threadIdx.x;
    const int tm  = tid >> 5;
    const int tn  = tid & 31;
    const int g   = blockIdx.y;
    const int bt0 = blockIdx.x * TM;

    // ---- load x tile (64 tokens x 64 d), transposed into xs[d][m] ----
    {
        const float* xg = x + (size_t)bt0 * GD + g * Dd;
#pragma unroll
        for (int it = 0; it < 4; it++) {
            int i  = it * 256 + tid;        // 0..1023
            int m  = i >> 4;                // token 0..63
            int d4 = i & 15;                // float4 index 0..15
            float4 v4 = *(const float4*)(xg + (size_t)m * GD + d4 * 4);
            xs[(d4 * 4 + 0) * PADM + m] = v4.x;
            xs[(d4 * 4 + 1) * PADM + m] = v4.y;
            xs[(d4 * 4 + 2) * PADM + m] = v4.z;
            xs[(d4 * 4 + 3) * PADM + m] = v4.w;
        }
        for (int i = tid; i < Vv; i += 256) csq[i] = g_csq[g * Vv + i];
    }

    float mind[8];
    int   minv[8];
#pragma unroll
    for (int i = 0; i < 8; i++) { mind[i] = 3.4e38f; minv[i] = 0; }

    const float* cbg = cb + g * Dd;

    for (int ch = 0; ch < NCHUNK; ch++) {
        __syncthreads();   // prior chunk's reads done before overwriting cs
        // ---- load codebook chunk [TN cwords x 64 d], transposed into cs[d][v] ----
        {
            const int vbase = ch * TN;
#pragma unroll
            for (int it = 0; it < 8; it++) {
                int i  = it * 256 + tid;    // 0..2047
                int vl = i & 127;           // lane-major v -> conflict-free STS
                int d4 = i >> 7;            // 0..15
                float4 c4 = *(const float4*)(cbg + (size_t)(vbase + vl) * GD + d4 * 4);
                cs[(d4 * 4 + 0) * TN + vl] = c4.x;
                cs[(d4 * 4 + 1) * TN + vl] = c4.y;
                cs[(d4 * 4 + 2) * TN + vl] = c4.z;
                cs[(d4 * 4 + 3) * TN + vl] = c4.w;
            }
        }
        __syncthreads();

        // acc2[tp][j]: packed dot for tokens (2tp, 2tp+1) x codeword j
        unsigned long long acc2[4][4];
#pragma unroll
        for (int i = 0; i < 4; i++)
#pragma unroll
            for (int j = 0; j < 4; j++) acc2[i][j] = 0ull;   // packed (0.f, 0.f)

        const float* asrc = xs + tm * 8;   // broadcast reads (all lanes same addr)
        const float* bsrc = cs + tn * 4;   // lanes stride 16B -> conflict-free
#pragma unroll 16
        for (int k = 0; k < Dd; k++) {
            // two LDS.128: 8 consecutive tokens -> 4 packed (m, m+1) pairs, free
            ulonglong2 aA = *(const ulonglong2*)(asrc + k * PADM);
            ulonglong2 aB = *(const ulonglong2*)(asrc + k * PADM + 4);
            float4 b      = *(const float4*)(bsrc + k * TN);
            unsigned long long ap[4] = {aA.x, aA.y, aB.x, aB.y};
            unsigned long long bp[4];
            PACK2DUP(bp[0], b.x);
            PACK2DUP(bp[1], b.y);
            PACK2DUP(bp[2], b.z);
            PACK2DUP(bp[3], b.w);
#pragma unroll
            for (int tp = 0; tp < 4; tp++)
#pragma unroll
                for (int j = 0; j < 4; j++)
                    FFMA2(acc2[tp][j], ap[tp], bp[j], acc2[tp][j]);
        }

        // dist = c_sq - 2*dot; running argmin (ascending v within thread)
        const int vb = ch * TN + tn * 4;
#pragma unroll
        for (int j = 0; j < 4; j++) {
            float cq = csq[vb + j];
#pragma unroll
            for (int tp = 0; tp < 4; tp++) {
                float dot_lo = __uint_as_float((unsigned)(acc2[tp][j]));
                float dot_hi = __uint_as_float((unsigned)(acc2[tp][j] >> 32));
                float d0 = fmaf(-2.f, dot_lo, cq);
                float d1 = fmaf(-2.f, dot_hi, cq);
                int i0 = 2 * tp, i1 = 2 * tp + 1;
                if (d0 < mind[i0]) { mind[i0] = d0; minv[i0] = vb + j; }
                if (d1 < mind[i1]) { mind[i1] = d1; minv[i1] = vb + j; }
            }
        }
    }

    // ---- warp argmin across 32 lanes (each warp = one tm row of 8 tokens) ----
#pragma unroll
    for (int i = 0; i < 8; i++) {
        float d = mind[i];
        int   v = minv[i];
        for (int off = 16; off; off >>= 1) {
            float d2 = __shfl_down_sync(0xffffffffu, d, off);
            int   v2 = __shfl_down_sync(0xffffffffu, v, off);
            if (d2 < d || (d2 == d && v2 < v)) { d = d2; v = v2; }
        }
        if (tn == 0) ids_s[tm * 8 + i] = v;
    }
    __syncthreads();

    // ---- ids output + mask ----
    if (tid < TM) {
        int bt = bt0 + tid;
        int p  = pad[bt];
        msk_s[tid] = p ? 0.f : 1.f;
        out[(size_t)bt * Gg + g] = p ? -1.0f : (float)ids_s[tid];
    }
    __syncthreads();

    // ---- quantized_st = q*mask, and masked ||q - x||^2 partial ----
    float ss = 0.f;
    {
        int tk   = tid >> 2;    // token 0..63 (4 threads per token)
        int part = tid & 3;
        int d0   = part * 16;
        int id   = ids_s[tk];
        float m  = msk_s[tk];
        int bt   = bt0 + tk;
        float*       qo = out + OUT_Q + ((size_t)bt * Gg + g) * Dd + d0;
        const float* qc = cb + (size_t)id * GD + g * Dd + d0;
#pragma unroll
        for (int q4 = 0; q4 < 4; q4++) {
            float4 qv = *(const float4*)(qc + q4 * 4);
            float xv0 = xs[(d0 + q4 * 4 + 0) * PADM + tk];
            float xv1 = xs[(d0 + q4 * 4 + 1) * PADM + tk];
            float xv2 = xs[(d0 + q4 * 4 + 2) * PADM + tk];
            float xv3 = xs[(d0 + q4 * 4 + 3) * PADM + tk];
            float e0 = qv.x - xv0, e1 = qv.y - xv1, e2 = qv.z - xv2, e3 = qv.w - xv3;
            ss += e0 * e0 + e1 * e1 + e2 * e2 + e3 * e3;
            float4 o;
            o.x = qv.x * m; o.y = qv.y * m; o.z = qv.z * m; o.w = qv.w * m;
            *(float4*)(qo + q4 * 4) = o;
        }
        ss *= m;
    }
    for (int off = 16; off; off >>= 1) ss += __shfl_down_sync(0xffffffffu, ss, off);
    if (tn == 0) red[tm] = ss;
    __syncthreads();
    if (tid == 0) {
        float s = 0.f;
#pragma unroll
        for (int i = 0; i < 8; i++) s += red[i];
        g_partials[blockIdx.y * gridDim.x + blockIdx.x] = s;
    }
}

// ---------------------------------------------------------------------------
// Kernel 2: final reduction -> 3 scalar losses
// ---------------------------------------------------------------------------
__global__ void final_kernel(const int* __restrict__ pad, float* __restrict__ out) {
    __shared__ float rs[256];
    __shared__ int   rc[256];
    int tid = threadIdx.x;
    float s = 0.f;
    for (int i = tid; i < 2048; i += 256) s += g_partials[i];
    int c = 0;
    for (int i = tid; i < BT; i += 256) c += (pad[i] == 0);
    rs[tid] = s; rc[tid] = c;
    __syncthreads();
    for (int off = 128; off; off >>= 1) {
        if (tid < off) { rs[tid] += rs[tid + off]; rc[tid] += rc[tid + off]; }
        __syncthreads();
    }
    if (tid == 0) {
        float denom = (float)rc[0];
        float k = rs[0] / denom;
        out[OUT_LOSS + 0] = k;        // kmeans_loss
        out[OUT_LOSS + 1] = k;        // commitment_loss (numerically identical)
        out[OUT_LOSS + 2] = k + k;    // total (BETA = 1)
    }
}

// ---------------------------------------------------------------------------
extern "C" void kernel_launch(void* const* d_in, const int* in_sizes, int n_in,
                              void* d_out, int out_size)
{
    const float* x   = (const float*)d_in[0];
    const int*   pad = (const int*)  d_in[1];
    const float* cb  = (const float*)d_in[2];
    float*       out = (float*)d_out;

    const int smem = (Dd * PADM + Dd * TN + Vv) * 4 + TM * 4 + TM * 4 + 8 * 4;
    cudaFuncSetAttribute(vq_kernel, cudaFuncAttributeMaxDynamicSharedMemorySize, smem);

    csq_kernel<<<32, 256>>>(cb);
    dim3 grid(BT / TM, Gg);
    vq_kernel<<<grid, 256, smem>>>(x, pad, cb, out);
    final_kernel<<<1, 256>>>(pad, out);
}

// round 7
// speedup vs baseline: 1.2973x; 1.2659x over previous
#include <cuda_runtime.h>
#include <cuda_bf16.h>
#include <cstdint>

// ---------------- problem constants ----------------
#define BT   16384
#define Gg   8
#define Dd   64
#define Vv   1024
#define GD   512
#define TM   128            // tokens per CTA
#define N_IDS (BT*Gg)
#define OUT_Q N_IDS
#define OUT_LOSS (N_IDS + BT*GD)

// extended-K layout: 6 slots x 64 bf16 = 384 bf16 = 48 x 16B units per row
#define KU    48
#define ROWB  768
#define NKS   24            // 384/16 k-steps
#define CHUNK_N 64
#define NCHUNK  16
#define CHUNK_B (CHUNK_N*ROWB)   // 49152

// ---------------- smem layout (bytes) ----------------
#define SM_A    0            // 128 x 768 = 98304
#define SM_B    98304        // 2 x 49152 = 98304
#define SM_CSQ  196608       // 1024 f32
#define SM_MD   200704       // 256 f32
#define SM_MV   201728       // 256 i32
#define SM_IDS  202752       // 128 i32
#define SM_MSK  203264       // 128 f32
#define SM_RED  203776       // 8 f32
#define SMEM_TOTAL 203840

// ---------------- device globals ----------------
__device__ float g_csq[Gg*Vv];
__device__ float g_partials[Gg*(BT/TM)];
// pre-split, pre-swizzled B_ext: [g][v] rows of 48 uint4 (16B units), unit u at pos u^(v&7)
__device__ __align__(16) uint4 g_cbs[Gg*Vv*KU];   // 6 MB

// ---------------- PTX helpers ----------------
__device__ __forceinline__ uint32_t smem_u32(const void* p) {
    uint32_t a;
    asm("{ .reg .u64 t; cvta.to.shared.u64 t, %1; cvt.u32.u64 %0, t; }" : "=r"(a) : "l"(p));
    return a;
}
#define LDSM4(r, addr) \
    asm volatile("ldmatrix.sync.aligned.m8n8.x4.shared.b16 {%0,%1,%2,%3}, [%4];" \
        : "=r"((r)[0]), "=r"((r)[1]), "=r"((r)[2]), "=r"((r)[3]) : "r"(addr))
#define MMA(c, a, b) \
    asm volatile("mma.sync.aligned.m16n8k16.row.col.f32.bf16.bf16.f32 " \
        "{%0,%1,%2,%3},{%4,%5,%6,%7},{%8,%9},{%0,%1,%2,%3};" \
        : "+f"((c)[0]), "+f"((c)[1]), "+f"((c)[2]), "+f"((c)[3]) \
        : "r"((a)[0]), "r"((a)[1]), "r"((a)[2]), "r"((a)[3]), "r"((b)[0]), "r"((b)[1]))
__device__ __forceinline__ void cp16(uint32_t dst, const void* src) {
    asm volatile("cp.async.cg.shared.global [%0], [%1], 16;" :: "r"(dst), "l"(src) : "memory");
}
#define CP_COMMIT()  asm volatile("cp.async.commit_group;" ::: "memory")
#define CP_WAIT(n)   asm volatile("cp.async.wait_group %0;" :: "n"(n) : "memory")

__device__ __forceinline__ void split3(float v, float& h, float& m, float& l) {
    h = __bfloat162float(__float2bfloat16_rn(v));
    float r1 = v - h;
    m = __bfloat162float(__float2bfloat16_rn(r1));
    l = r1 - m;   // bf16-rounded at pack time
}
__device__ __forceinline__ uint32_t pack_bf2(float lo, float hi) {
    uint32_t u;
    asm("cvt.rn.bf16x2.f32 %0, %1, %2;" : "=r"(u) : "f"(hi), "f"(lo));
    return u;
}

// ---------------------------------------------------------------------------
// Kernel 0: c_sq[g][v]
// ---------------------------------------------------------------------------
__global__ void csq_kernel(const float* __restrict__ cb) {
    int idx = blockIdx.x * blockDim.x + threadIdx.x;
    if (idx >= Vv * Gg) return;
    int v = idx >> 3, g = idx & 7;
    const float4* p = (const float4*)(cb + (size_t)v * GD + g * Dd);
    float s = 0.f;
#pragma unroll
    for (int i = 0; i < 16; i++) {
        float4 c = p[i];
        s = fmaf(c.x, c.x, s); s = fmaf(c.y, c.y, s);
        s = fmaf(c.z, c.z, s); s = fmaf(c.w, c.w, s);
    }
    g_csq[g * Vv + v] = s;
}

// ---------------------------------------------------------------------------
// Kernel P: build B_ext (split h/m/l, K-slots [h,m,h,l,h,m], pre-swizzled)
// ---------------------------------------------------------------------------
__global__ void prep_kernel(const float* __restrict__ cb) {
    int idx = blockIdx.x * blockDim.x + threadIdx.x;   // 0..8191 = g*1024+v
    if (idx >= Gg * Vv) return;
    int g = idx >> 10, v = idx & 1023;
    const float* src = cb + (size_t)v * GD + g * Dd;
    uint4* row = g_cbs + (size_t)idx * KU;
    int r7 = v & 7;
#pragma unroll
    for (int uu = 0; uu < 8; uu++) {
        uint32_t ph[4], pm[4], pl[4];
#pragma unroll
        for (int j = 0; j < 4; j++) {
            float a = src[uu * 8 + j * 2];
            float b = src[uu * 8 + j * 2 + 1];
            float ha, ma, la, hb, mb, lb;
            split3(a, ha, ma, la);
            split3(b, hb, mb, lb);
            ph[j] = pack_bf2(ha, hb);
            pm[j] = pack_bf2(ma, mb);
            pl[j] = pack_bf2(la, lb);
        }
        uint4 H = make_uint4(ph[0], ph[1], ph[2], ph[3]);
        uint4 M = make_uint4(pm[0], pm[1], pm[2], pm[3]);
        uint4 L = make_uint4(pl[0], pl[1], pl[2], pl[3]);
        // B slots: [h, m, h, l, h, m]
        row[(0 * 8 + uu) ^ r7] = H;
        row[(1 * 8 + uu) ^ r7] = M;
        row[(2 * 8 + uu) ^ r7] = H;
        row[(3 * 8 + uu) ^ r7] = L;
        row[(4 * 8 + uu) ^ r7] = H;
        row[(5 * 8 + uu) ^ r7] = M;
    }
}

// ---------------------------------------------------------------------------
// Main VQ kernel: 256 threads, 8 warps (4 M x 2 N), smem 203840 B
// ---------------------------------------------------------------------------
__global__ __launch_bounds__(256, 1)
void vq_kernel(const float* __restrict__ x, const int* __restrict__ pad,
               const float* __restrict__ cb, float* __restrict__ out)
{
    extern __shared__ char sm[];
    const uint32_t sbase = smem_u32(sm);
    const int tid  = threadIdx.x;
    const int wid  = tid >> 5;
    const int lane = tid & 31;
    const int g    = blockIdx.y;
    const int bt0  = blockIdx.x * TM;
    float* csq_sm  = (float*)(sm + SM_CSQ);

    // ---- build A_ext: split x tile into slots [h,h,m,h,l,m], swizzled ----
    {
        int t = tid >> 1, hf = tid & 1;
        const float* xp = x + (size_t)(bt0 + t) * GD + g * Dd + hf * 32;
        uint32_t rowbase = (uint32_t)t * ROWB;
        int r7 = t & 7;
#pragma unroll
        for (int q = 0; q < 16; q++) {
            float a = xp[2 * q], b = xp[2 * q + 1];
            float ha, ma, la, hb, mb, lb;
            split3(a, ha, ma, la);
            split3(b, hb, mb, lb);
            uint32_t ph = pack_bf2(ha, hb);
            uint32_t pm = pack_bf2(ma, mb);
            uint32_t pl = pack_bf2(la, lb);
            int p  = hf * 16 + q;      // pair index 0..31
            int uu = p >> 2;           // unit within slot
            int iw = (p & 3) * 4;      // byte within unit
            // A slots: [h, h, m, h, l, m]
            *(uint32_t*)(sm + SM_A + rowbase + ((((0*8)+uu) ^ r7) << 4) + iw) = ph;
            *(uint32_t*)(sm + SM_A + rowbase + ((((1*8)+uu) ^ r7) << 4) + iw) = ph;
            *(uint32_t*)(sm + SM_A + rowbase + ((((2*8)+uu) ^ r7) << 4) + iw) = pm;
            *(uint32_t*)(sm + SM_A + rowbase + ((((3*8)+uu) ^ r7) << 4) + iw) = ph;
            *(uint32_t*)(sm + SM_A + rowbase + ((((4*8)+uu) ^ r7) << 4) + iw) = pl;
            *(uint32_t*)(sm + SM_A + rowbase + ((((5*8)+uu) ^ r7) << 4) + iw) = pm;
        }
    }
    for (int i = tid; i < Vv; i += 256) csq_sm[i] = g_csq[g * Vv + i];

    const char* cbs_g = (const char*)(g_cbs + (size_t)g * Vv * KU);

    // prefetch chunk 0
    {
        uint32_t dst = sbase + SM_B + (uint32_t)tid * 16;
        const char* src = cbs_g + (size_t)tid * 16;
#pragma unroll
        for (int i = 0; i < 12; i++)
            cp16(dst + i * 4096, src + i * 4096);
        CP_COMMIT();
    }
    __syncthreads();

    // ---- per-warp geometry ----
    const int wm = (wid & 3) * 32;      // warp M base (token row in tile)
    const int wn = (wid >> 2) * 32;     // warp N base (within 64-wide chunk)
    const int lq = lane >> 3;           // ldmatrix matrix id
    const int lr = lane & 7;            // row-in-matrix (== row&7 for all tiles)
    const uint32_t aptr0 = sbase + SM_A + (uint32_t)(wm + (lq & 1) * 8 + lr) * ROWB;
    const uint32_t aptr1 = aptr0 + 16 * ROWB;
    const uint32_t aksel = (uint32_t)(lq >> 1);
    const uint32_t bksel = (uint32_t)(lq & 1);
    const uint32_t brow  = (uint32_t)(wn + (lq >> 1) * 8 + lr) * ROWB;

    float mind[4];
    int   minv[4];
#pragma unroll
    for (int s = 0; s < 4; s++) { mind[s] = __int_as_float(0x7f800000); minv[s] = 0; }

    for (int c = 0; c < NCHUNK; c++) {
        if (c + 1 < NCHUNK) {
            uint32_t dst = sbase + SM_B + (uint32_t)(((c + 1) & 1) * CHUNK_B) + (uint32_t)tid * 16;
            const char* src = cbs_g + (size_t)(c + 1) * CHUNK_B + (size_t)tid * 16;
#pragma unroll
            for (int i = 0; i < 12; i++)
                cp16(dst + i * 4096, src + i * 4096);
            CP_COMMIT();
            CP_WAIT(1);
        } else {
            CP_WAIT(0);
        }
        __syncthreads();

        float cc[2][4][4];
#pragma unroll
        for (int mt = 0; mt < 2; mt++)
#pragma unroll
            for (int nt = 0; nt < 4; nt++)
#pragma unroll
                for (int r = 0; r < 4; r++) cc[mt][nt][r] = 0.f;

        const uint32_t bptr0 = sbase + SM_B + (uint32_t)((c & 1) * CHUNK_B) + brow;
        const uint32_t bptr1 = bptr0 + 16 * ROWB;
#pragma unroll
        for (int ks = 0; ks < NKS; ks++) {
            uint32_t offa = (((2u * ks + aksel) ^ (uint32_t)lr) << 4);
            uint32_t offb = (((2u * ks + bksel) ^ (uint32_t)lr) << 4);
            uint32_t a[8], b[8];
            LDSM4(a + 0, aptr0 + offa);
            LDSM4(a + 4, aptr1 + offa);
            LDSM4(b + 0, bptr0 + offb);
            LDSM4(b + 4, bptr1 + offb);
#pragma unroll
            for (int mt = 0; mt < 2; mt++) {
                MMA(cc[mt][0], a + mt * 4, b + 0);
                MMA(cc[mt][1], a + mt * 4, b + 2);
                MMA(cc[mt][2], a + mt * 4, b + 4);
                MMA(cc[mt][3], a + mt * 4, b + 6);
            }
        }

        // dist = csq - 2*dot; running argmin (ascending v for deterministic ties)
        const int colb = c * CHUNK_N + wn + 2 * (lane & 3);
#pragma unroll
        for (int nt = 0; nt < 4; nt++) {
            int v0 = colb + nt * 8;
            float q0 = csq_sm[v0], q1 = csq_sm[v0 + 1];
#pragma unroll
            for (int mt = 0; mt < 2; mt++) {
                float d0 = fmaf(-2.f, cc[mt][nt][0], q0);
                float d1 = fmaf(-2.f, cc[mt][nt][1], q1);
                float d2 = fmaf(-2.f, cc[mt][nt][2], q0);
                float d3 = fmaf(-2.f, cc[mt][nt][3], q1);
                int s0 = mt * 2, s1 = mt * 2 + 1;
                if (d0 < mind[s0]) { mind[s0] = d0; minv[s0] = v0; }
                if (d1 < mind[s0]) { mind[s0] = d1; minv[s0] = v0 + 1; }
                if (d2 < mind[s1]) { mind[s1] = d2; minv[s1] = v0; }
                if (d3 < mind[s1]) { mind[s1] = d3; minv[s1] = v0 + 1; }
            }
        }
        __syncthreads();   // compute done before next prefetch overwrites buffer
    }

    // ---- reduce within lane-quads (same token row), write per-N-half ----
#pragma unroll
    for (int s = 0; s < 4; s++) {
        float d = mind[s]; int v = minv[s];
        float d2 = __shfl_xor_sync(0xffffffffu, d, 1);
        int   v2 = __shfl_xor_sync(0xffffffffu, v, 1);
        if (d2 < d || (d2 == d && v2 < v)) { d = d2; v = v2; }
        d2 = __shfl_xor_sync(0xffffffffu, d, 2);
        v2 = __shfl_xor_sync(0xffffffffu, v, 2);
        if (d2 < d || (d2 == d && v2 < v)) { d = d2; v = v2; }
        if ((lane & 3) == 0) {
            int row = wm + (s >> 1) * 16 + (s & 1) * 8 + (lane >> 2);
            ((float*)(sm + SM_MD))[(wid >> 2) * 128 + row] = d;
            ((int*)  (sm + SM_MV))[(wid >> 2) * 128 + row] = v;
        }
    }
    __syncthreads();

    // ---- combine N-halves, emit ids + mask ----
    if (tid < TM) {
        float d0 = ((float*)(sm + SM_MD))[tid];
        float d1 = ((float*)(sm + SM_MD))[128 + tid];
        int   v0 = ((int*)(sm + SM_MV))[tid];
        int   v1 = ((int*)(sm + SM_MV))[128 + tid];
        int v = (d1 < d0 || (d1 == d0 && v1 < v0)) ? v1 : v0;
        int bt = bt0 + tid;
        int p  = pad[bt];
        ((int*)(sm + SM_IDS))[tid]   = v;
        ((float*)(sm + SM_MSK))[tid] = p ? 0.f : 1.f;
        out[(size_t)bt * Gg + g] = p ? -1.0f : (float)v;
    }
    __syncthreads();

    // ---- quantized = q*mask + masked ||q-x||^2 partial (exact f32 from global) ----
    float ss = 0.f;
    {
        int tk = tid >> 1, hf = tid & 1, d0 = hf * 32;
        int id  = ((int*)(sm + SM_IDS))[tk];
        float m = ((float*)(sm + SM_MSK))[tk];
        int bt  = bt0 + tk;
        const float* qc = cb + (size_t)id * GD + g * Dd + d0;
        const float* xr = x  + (size_t)bt * GD + g * Dd + d0;
        float* qo = out + OUT_Q + ((size_t)bt * Gg + g) * Dd + d0;
#pragma unroll
        for (int q4 = 0; q4 < 8; q4++) {
            float4 qv = *(const float4*)(qc + q4 * 4);
            float4 xv = *(const float4*)(xr + q4 * 4);
            float e0 = qv.x - xv.x, e1 = qv.y - xv.y, e2 = qv.z - xv.z, e3 = qv.w - xv.w;
            ss += e0*e0 + e1*e1 + e2*e2 + e3*e3;
            float4 o; o.x = qv.x*m; o.y = qv.y*m; o.z = qv.z*m; o.w = qv.w*m;
            *(float4*)(qo + q4 * 4) = o;
        }
        ss *= m;
    }
    for (int off = 16; off; off >>= 1) ss += __shfl_down_sync(0xffffffffu, ss, off);
    if ((tid & 31) == 0) ((float*)(sm + SM_RED))[wid] = ss;
    __syncthreads();
    if (tid == 0) {
        float s = 0.f;
#pragma unroll
        for (int i = 0; i < 8; i++) s += ((float*)(sm + SM_RED))[i];
        g_partials[g * gridDim.x + blockIdx.x] = s;
    }
}

// ---------------------------------------------------------------------------
// Final reduction
// ---------------------------------------------------------------------------
__global__ void final_kernel(const int* __restrict__ pad, float* __restrict__ out) {
    __shared__ float rs[256];
    __shared__ int   rc[256];
    int tid = threadIdx.x;
    float s = 0.f;
    for (int i = tid; i < Gg * (BT / TM); i += 256) s += g_partials[i];
    int c = 0;
    for (int i = tid; i < BT; i += 256) c += (pad[i] == 0);
    rs[tid] = s; rc[tid] = c;
    __syncthreads();
    for (int off = 128; off; off >>= 1) {
        if (tid < off) { rs[tid] += rs[tid + off]; rc[tid] += rc[tid + off]; }
        __syncthreads();
    }
    if (tid == 0) {
        float k = rs[0] / (float)rc[0];
        out[OUT_LOSS + 0] = k;
        out[OUT_LOSS + 1] = k;
        out[OUT_LOSS + 2] = k + k;
    }
}

// ---------------------------------------------------------------------------
extern "C" void kernel_launch(void* const* d_in, const int* in_sizes, int n_in,
                              void* d_out, int out_size)
{
    const float* x   = (const float*)d_in[0];
    const int*   pad = (const int*)  d_in[1];
    const float* cb  = (const float*)d_in[2];
    float*       out = (float*)d_out;

    cudaFuncSetAttribute(vq_kernel, cudaFuncAttributeMaxDynamicSharedMemorySize, SMEM_TOTAL);

    csq_kernel<<<32, 256>>>(cb);
    prep_kernel<<<32, 256>>>(cb);
    dim3 grid(BT / TM, Gg);
    vq_kernel<<<grid, 256, SMEM_TOTAL>>>(x, pad, cb, out);
    final_kernel<<<1, 256>>>(pad, out);
}